// round 6
// baseline (speedup 1.0000x reference)
#include <cuda_runtime.h>

// NeighborlistForInference: brute-force N^2 upper-triangular pair list.
//
// Output layout (fp32, 6*P elements, P = n(n-1)/2):
//   [0   ,  P) : i index per pair (-1 if out of cutoff)
//   [P   , 2P) : j index per pair (-1)
//   [2P  , 3P) : d_ij (0)
//   [3P  , 6P) : r_ij row-major [P,3] (0)
//
// Round-5: kill the L1 global-load wavefront bottleneck (was 75% L1).
// Each block owns 1024 consecutive pairs. Positions pos[j] are staged into
// shared memory SoA arrays indexed by block-local PAIR offset q = p - base:
// staging per row segment is a contiguous coalesced copy, and each thread
// then reads its 4 pairs with three conflict-free LDS.128 (slots 4t..4t+3).
// Stores remain 6 x STG.128 (.cs). Math identical to R4 (rel_err 3e-8).

#ifndef NL_CUTOFF
#define NL_CUTOFF 0.5f
#endif

#define BLOCK_THREADS   256
#define PAIRS_PER_BLOCK 1024

__device__ __forceinline__ int tri_start(int i, int n) {
    return (i * (2 * n - i - 1)) >> 1;     // row start, max ~36M fits int32
}

__device__ __forceinline__ int tri_row(int p, int n) {
    // row i with tri_start(i) <= p < tri_start(i+1); sqrt estimate + exact fixup
    const int a = 2 * n - 1;
    const int disc = a * a - 8 * p;
    int i = (int)(0.5f * ((float)a - sqrtf((float)disc)));
    if (i < 0) i = 0;
    if (i > n - 2) i = n - 2;
    while (p < tri_start(i, n)) --i;
    while (i < n - 2 && p >= tri_start(i + 1, n)) ++i;
    return i;
}

__global__ __launch_bounds__(BLOCK_THREADS)
void neighborlist_kernel(const float* __restrict__ pos,
                         const float* __restrict__ box,
                         const int*   __restrict__ is_periodic,
                         float* __restrict__ out_i,
                         float* __restrict__ out_j,
                         float* __restrict__ out_d,
                         float* __restrict__ out_r,
                         int n, int P)
{
    __shared__ __align__(16) float xs[PAIRS_PER_BLOCK];
    __shared__ __align__(16) float ys[PAIRS_PER_BLOCK];
    __shared__ __align__(16) float zs[PAIRS_PER_BLOCK];

    const int base    = blockIdx.x * PAIRS_PER_BLOCK;
    const int m_total = min(PAIRS_PER_BLOCK, P - base);

    // ---- staging: copy pos[j] for every pair slot q in [0, m_total),
    // segment by row (j contiguous within a row). Uniform control flow.
    {
        int q = 0;
        int i = tri_row(base, n);
        while (q < m_total) {
            const int rs      = tri_start(i, n);
            const int row_len = n - 1 - i;                       // pairs in row i
            const int p       = base + q;
            const int seg     = min(base + m_total, rs + row_len) - p;
            const int j0      = i + 1 + (p - rs);
            for (int d = threadIdx.x; d < seg; d += BLOCK_THREADS) {
                const int g = 3 * (j0 + d);
                xs[q + d] = pos[g + 0];
                ys[q + d] = pos[g + 1];
                zs[q + d] = pos[g + 2];
            }
            q += seg;
            ++i;
        }
    }
    __syncthreads();

    // ---- processing: thread t owns pairs p0..p0+3 = slots 4t..4t+3
    const int p0 = base + 4 * threadIdx.x;
    if (p0 >= P) return;                    // P % 4 == 0 -> whole thread in/out

    int i = tri_row(p0, n);
    int j = i + 1 + (p0 - tri_start(i, n));

    const float Lx = box[0], Ly = box[4], Lz = box[8];
    const float hx = 0.5f * Lx, hy = 0.5f * Ly, hz = 0.5f * Lz;
    const int per = *is_periodic;

    float xi = pos[3 * i + 0], yi = pos[3 * i + 1], zi = pos[3 * i + 2];
    float fi_f = (float)i;
    float fj_f = (float)j;

    // conflict-free, 16B-aligned vector reads of this thread's 4 slots
    const int s = 4 * threadIdx.x;
    float jx[4], jy[4], jz[4];
    *(float4*)jx = *(const float4*)&xs[s];
    *(float4*)jy = *(const float4*)&ys[s];
    *(float4*)jz = *(const float4*)&zs[s];

    float fi[4], fj[4], fd[4], rx[4], ry[4], rz[4];

    #pragma unroll
    for (int k = 0; k < 4; ++k) {
        if (j >= n) {                       // rare row crossing
            ++i; j = i + 1;
            xi = pos[3 * i + 0]; yi = pos[3 * i + 1]; zi = pos[3 * i + 2];
            fi_f = (float)i; fj_f = (float)j;
        }
        float dx = xi - jx[k];
        float dy = yi - jy[k];
        float dz = zi - jz[k];
        if (per) {
            // exact minimum-image for r in (-L, L): t in (-L/2, 3L/2)
            float tx = dx + hx; tx = (tx >= Lx) ? tx - Lx : tx; tx = (tx < 0.0f) ? tx + Lx : tx; dx = tx - hx;
            float ty = dy + hy; ty = (ty >= Ly) ? ty - Ly : ty; ty = (ty < 0.0f) ? ty + Ly : ty; dy = ty - hy;
            float tz = dz + hz; tz = (tz >= Lz) ? tz - Lz : tz; tz = (tz < 0.0f) ? tz + Lz : tz; dz = tz - hz;
        }
        const float d  = sqrtf(dx * dx + dy * dy + dz * dz);   // IEEE
        const bool  in = (d <= NL_CUTOFF);
        fi[k] = in ? fi_f : -1.0f;
        fj[k] = in ? fj_f : -1.0f;
        fd[k] = in ? d    :  0.0f;
        rx[k] = in ? dx : 0.0f;
        ry[k] = in ? dy : 0.0f;
        rz[k] = in ? dz : 0.0f;
        ++j; fj_f += 1.0f;                  // exact: j < 2^24
    }

    // P % 4 == 0 -> all six stream addresses 16B-aligned
    __stcs((float4*)(out_i + p0), make_float4(fi[0], fi[1], fi[2], fi[3]));
    __stcs((float4*)(out_j + p0), make_float4(fj[0], fj[1], fj[2], fj[3]));
    __stcs((float4*)(out_d + p0), make_float4(fd[0], fd[1], fd[2], fd[3]));
    float* rb = out_r + 3 * p0;             // 12 floats per thread, 16B-aligned
    __stcs((float4*)(rb + 0), make_float4(rx[0], ry[0], rz[0], rx[1]));
    __stcs((float4*)(rb + 4), make_float4(ry[1], rz[1], rx[2], ry[2]));
    __stcs((float4*)(rb + 8), make_float4(rz[2], rx[3], ry[3], rz[3]));
}

extern "C" void kernel_launch(void* const* d_in, const int* in_sizes, int n_in,
                              void* d_out, int out_size)
{
    const float* pos   = (const float*)d_in[0];
    const float* box   = (const float*)d_in[1];
    const int*   isper = (const int*)d_in[2];
    float*       out   = (float*)d_out;

    const int n = in_sizes[0] / 3;
    const int P = (int)((long long)n * (n - 1) / 2);   // 17,997,000 for n=6000

    const int grid = (P + PAIRS_PER_BLOCK - 1) / PAIRS_PER_BLOCK;
    neighborlist_kernel<<<grid, BLOCK_THREADS>>>(pos, box, isper,
                                                 out,
                                                 out + P,
                                                 out + 2 * (size_t)P,
                                                 out + 3 * (size_t)P,
                                                 n, P);
}

// round 7
// speedup vs baseline: 1.4830x; 1.4830x over previous
#include <cuda_runtime.h>

// NeighborlistForInference: brute-force N^2 upper-triangular pair list.
//
// Output layout (fp32, 6*P elements, P = n(n-1)/2):
//   [0   ,  P) : i index per pair (-1 if out of cutoff)
//   [P   , 2P) : j index per pair (-1)
//   [2P  , 3P) : d_ij (0)
//   [3P  , 6P) : r_ij row-major [P,3] (0)
//
// Round-6: strided warp mapping. Warp w owns pairs [128w, 128w+128);
// thread t handles p = 128w + t + 32m, m=0..3. Consecutive lanes are 1 j
// apart, so every pos[j] component load spans only 3 cache lines per
// instruction (vs 12 with blocked mapping) -> 4x fewer load wavefronts.
// Stores are scalar but perfectly coalesced (1 line per STG for i/j/d,
// 3 lines for r). No shared memory. Math identical to R4 (rel_err 3e-8).

#ifndef NL_CUTOFF
#define NL_CUTOFF 0.5f
#endif

#define BLOCK_THREADS 256   // 8 warps * 128 pairs = 1024 pairs per block

__device__ __forceinline__ int tri_start(int i, int n) {
    return (i * (2 * n - i - 1)) >> 1;     // row start, max ~36M fits int32
}

__device__ __forceinline__ int tri_row(int p, int n) {
    // row i with tri_start(i) <= p < tri_start(i+1); sqrt estimate + exact fixup
    const int a = 2 * n - 1;
    const int disc = a * a - 8 * p;
    int i = (int)(0.5f * ((float)a - sqrtf((float)disc)));
    if (i < 0) i = 0;
    if (i > n - 2) i = n - 2;
    while (p < tri_start(i, n)) --i;
    while (i < n - 2 && p >= tri_start(i + 1, n)) ++i;
    return i;
}

__global__ __launch_bounds__(BLOCK_THREADS)
void neighborlist_kernel(const float* __restrict__ pos,
                         const float* __restrict__ box,
                         const int*   __restrict__ is_periodic,
                         float* __restrict__ out_i,
                         float* __restrict__ out_j,
                         float* __restrict__ out_d,
                         float* __restrict__ out_r,
                         int n, int P)
{
    const int warp  = (blockIdx.x * BLOCK_THREADS + threadIdx.x) >> 5;
    const int lane  = threadIdx.x & 31;
    int p = warp * 128 + lane;
    if (p >= P) return;

    // ---- triangular index for first pair; then advance incrementally
    int i  = tri_row(p, n);
    int rs = tri_start(i, n);
    int j  = i + 1 + (p - rs);

    const float Lx = box[0], Ly = box[4], Lz = box[8];
    const float hx = 0.5f * Lx, hy = 0.5f * Ly, hz = 0.5f * Lz;
    const int per = *is_periodic;

    float xi = pos[3 * i + 0], yi = pos[3 * i + 1], zi = pos[3 * i + 2];
    float fi_f = (float)i;
    float fj_f = (float)j;

    #pragma unroll
    for (int m = 0; m < 4; ++m) {
        if (m) {
            p += 32;
            if (p >= P) break;
            j += 32; fj_f += 32.0f;         // exact: j < 2^24
            if (j >= n) {                   // row crossing(s)
                do {
                    rs += n - 1 - i;        // advance past row i
                    ++i;
                    j = i + 1 + (p - rs);
                } while (j >= n);
                xi = pos[3 * i + 0]; yi = pos[3 * i + 1]; zi = pos[3 * i + 2];
                fi_f = (float)i; fj_f = (float)j;
            }
        }

        // consecutive lanes: consecutive j -> 12B lane stride, 3 lines/LDG
        float dx = xi - pos[3 * j + 0];
        float dy = yi - pos[3 * j + 1];
        float dz = zi - pos[3 * j + 2];
        if (per) {
            // exact minimum-image for r in (-L, L): t in (-L/2, 3L/2)
            float tx = dx + hx; tx = (tx >= Lx) ? tx - Lx : tx; tx = (tx < 0.0f) ? tx + Lx : tx; dx = tx - hx;
            float ty = dy + hy; ty = (ty >= Ly) ? ty - Ly : ty; ty = (ty < 0.0f) ? ty + Ly : ty; dy = ty - hy;
            float tz = dz + hz; tz = (tz >= Lz) ? tz - Lz : tz; tz = (tz < 0.0f) ? tz + Lz : tz; dz = tz - hz;
        }
        const float d  = sqrtf(dx * dx + dy * dy + dz * dz);   // IEEE
        const bool  in = (d <= NL_CUTOFF);

        // scalar streaming stores, lane-contiguous -> coalesced
        __stcs(out_i + p, in ? fi_f : -1.0f);
        __stcs(out_j + p, in ? fj_f : -1.0f);
        __stcs(out_d + p, in ? d    :  0.0f);
        float* rb = out_r + 3 * p;
        __stcs(rb + 0, in ? dx : 0.0f);
        __stcs(rb + 1, in ? dy : 0.0f);
        __stcs(rb + 2, in ? dz : 0.0f);
    }
}

extern "C" void kernel_launch(void* const* d_in, const int* in_sizes, int n_in,
                              void* d_out, int out_size)
{
    const float* pos   = (const float*)d_in[0];
    const float* box   = (const float*)d_in[1];
    const int*   isper = (const int*)d_in[2];
    float*       out   = (float*)d_out;

    const int n = in_sizes[0] / 3;
    const int P = (int)((long long)n * (n - 1) / 2);   // 17,997,000 for n=6000

    const int pairs_per_block = BLOCK_THREADS * 4;     // 1024
    const int grid = (P + pairs_per_block - 1) / pairs_per_block;
    neighborlist_kernel<<<grid, BLOCK_THREADS>>>(pos, box, isper,
                                                 out,
                                                 out + P,
                                                 out + 2 * (size_t)P,
                                                 out + 3 * (size_t)P,
                                                 n, P);
}